// round 1
// baseline (speedup 1.0000x reference)
#include <cuda_runtime.h>
#include <math.h>

// Problem constants
#define B_    128
#define S_    256
#define D_    1536
#define DIN_  768
#define NH_   8
#define DH_   192
#define FF_   2048
#define BS_   (B_*S_)   // 32768

// ---------------- scratch (device globals; no cudaMalloc allowed) -------------
__device__ float g_t0 [B_*D_];
__device__ float g_v  [B_*D_];
__device__ float g_sa [B_*D_];
__device__ float g_t1 [B_*D_];
__device__ float g_qp [B_*D_];
__device__ float g_g  [B_*NH_*D_];
__device__ float g_scores[B_*NH_*S_];
__device__ float g_mt [B_*NH_*D_];
__device__ float g_o  [B_*D_];
__device__ float g_ca [B_*D_];
__device__ float g_t2 [B_*D_];
__device__ float g_h1 [B_*FF_];
__device__ float g_ff [B_*D_];
__device__ float g_t3 [B_*D_];
__device__ float g_xsq[B_*D_];
__device__ float g_qp2[B_*D_];
__device__ float g_qt [B_*D_];
__device__ float g_A  [2*B_*D_];
__device__ float g_S  [(size_t)2*B_*BS_];   // rows 0..127: scores, 128..255: raw cosine dots
__device__ float g_nm [B_*S_];
__device__ float g_nx [B_];

// ---------------- generic tiled GEMMs (fp32) ----------------------------------
// C(M,N) = A(M,K) @ W(N,K)^T + bias ; all dims assumed divisible by tiles.
template<int BM,int BN,int BK,int TM,int TN,bool RELU>
__global__ void __launch_bounds__(256) gemm_nt(
    const float* __restrict__ A, int lda,
    const float* __restrict__ W, int ldw,
    const float* __restrict__ bias,
    float* __restrict__ C, int ldc, int K)
{
    __shared__ float sA[BK][BM];
    __shared__ float sW[BK][BN];
    const int tid = threadIdx.x;
    const int bm = blockIdx.y*BM, bn = blockIdx.x*BN;
    const int tx = tid % (BN/TN), ty = tid / (BN/TN);
    float acc[TM][TN];
    #pragma unroll
    for (int i=0;i<TM;i++)
        #pragma unroll
        for (int j=0;j<TN;j++) acc[i][j]=0.f;

    for (int k0=0;k0<K;k0+=BK) {
        for (int i=tid;i<BM*(BK/4);i+=256) {
            int r=i/(BK/4), kv=i%(BK/4);
            float4 v=*(const float4*)(A+(size_t)(bm+r)*lda + k0 + kv*4);
            sA[kv*4+0][r]=v.x; sA[kv*4+1][r]=v.y; sA[kv*4+2][r]=v.z; sA[kv*4+3][r]=v.w;
        }
        for (int i=tid;i<BN*(BK/4);i+=256) {
            int r=i/(BK/4), kv=i%(BK/4);
            float4 v=*(const float4*)(W+(size_t)(bn+r)*ldw + k0 + kv*4);
            sW[kv*4+0][r]=v.x; sW[kv*4+1][r]=v.y; sW[kv*4+2][r]=v.z; sW[kv*4+3][r]=v.w;
        }
        __syncthreads();
        #pragma unroll
        for (int kk=0;kk<BK;kk++) {
            float a[TM], w[TN];
            #pragma unroll
            for (int i=0;i<TM;i+=4) *(float4*)&a[i] = *(const float4*)&sA[kk][ty*TM+i];
            #pragma unroll
            for (int j=0;j<TN;j+=4) *(float4*)&w[j] = *(const float4*)&sW[kk][tx*TN+j];
            #pragma unroll
            for (int i=0;i<TM;i++)
                #pragma unroll
                for (int j=0;j<TN;j++) acc[i][j] = fmaf(a[i], w[j], acc[i][j]);
        }
        __syncthreads();
    }
    #pragma unroll
    for (int i=0;i<TM;i++) {
        int gm = bm + ty*TM + i;
        #pragma unroll
        for (int j=0;j<TN;j++) {
            int gn = bn + tx*TN + j;
            float v = acc[i][j] + (bias ? bias[gn] : 0.f);
            if (RELU) v = fmaxf(v, 0.f);
            C[(size_t)gm*ldc + gn] = v;
        }
    }
}

// C(M,N) = A(M,K) @ W(K,N) + bias   (W row-major K x N)
template<int BM,int BN,int BK,int TM,int TN>
__global__ void __launch_bounds__(256) gemm_nn(
    const float* __restrict__ A, int lda,
    const float* __restrict__ W, int ldw,
    const float* __restrict__ bias,
    float* __restrict__ C, int ldc, int K)
{
    __shared__ float sA[BK][BM];
    __shared__ float sW[BK][BN];
    const int tid = threadIdx.x;
    const int bm = blockIdx.y*BM, bn = blockIdx.x*BN;
    const int tx = tid % (BN/TN), ty = tid / (BN/TN);
    float acc[TM][TN];
    #pragma unroll
    for (int i=0;i<TM;i++)
        #pragma unroll
        for (int j=0;j<TN;j++) acc[i][j]=0.f;

    for (int k0=0;k0<K;k0+=BK) {
        for (int i=tid;i<BM*(BK/4);i+=256) {
            int r=i/(BK/4), kv=i%(BK/4);
            float4 v=*(const float4*)(A+(size_t)(bm+r)*lda + k0 + kv*4);
            sA[kv*4+0][r]=v.x; sA[kv*4+1][r]=v.y; sA[kv*4+2][r]=v.z; sA[kv*4+3][r]=v.w;
        }
        for (int i=tid;i<BK*(BN/4);i+=256) {
            int kk=i/(BN/4), nv=i%(BN/4);
            *(float4*)&sW[kk][nv*4] = *(const float4*)(W+(size_t)(k0+kk)*ldw + bn + nv*4);
        }
        __syncthreads();
        #pragma unroll
        for (int kk=0;kk<BK;kk++) {
            float a[TM], w[TN];
            #pragma unroll
            for (int i=0;i<TM;i+=4) *(float4*)&a[i] = *(const float4*)&sA[kk][ty*TM+i];
            #pragma unroll
            for (int j=0;j<TN;j+=4) *(float4*)&w[j] = *(const float4*)&sW[kk][tx*TN+j];
            #pragma unroll
            for (int i=0;i<TM;i++)
                #pragma unroll
                for (int j=0;j<TN;j++) acc[i][j] = fmaf(a[i], w[j], acc[i][j]);
        }
        __syncthreads();
    }
    #pragma unroll
    for (int i=0;i<TM;i++) {
        int gm = bm + ty*TM + i;
        #pragma unroll
        for (int j=0;j<TN;j++) {
            int gn = bn + tx*TN + j;
            C[(size_t)gm*ldc + gn] = acc[i][j] + (bias ? bias[gn] : 0.f);
        }
    }
}

// ---------------- LayerNorm(+residual) over rows of length D_ ------------------
__global__ void __launch_bounds__(256) ln_kernel(
    const float* __restrict__ a, const float* __restrict__ r,
    const float* __restrict__ w, const float* __restrict__ bb,
    float* __restrict__ out, float* __restrict__ norm_out)
{
    const int row = blockIdx.x, tid = threadIdx.x;
    const float* ap = a + (size_t)row*D_;
    const float* rp = r ? r + (size_t)row*D_ : nullptr;
    float vals[6]; float s1=0.f, s2=0.f;
    #pragma unroll
    for (int i=0;i<6;i++) {
        int e = tid + i*256;
        float v = ap[e] + (rp ? rp[e] : 0.f);
        vals[i]=v; s1+=v; s2+=v*v;
    }
    __shared__ float red[16];
    int lane=tid&31, wid=tid>>5;
    for (int o=16;o;o>>=1){ s1+=__shfl_xor_sync(~0u,s1,o); s2+=__shfl_xor_sync(~0u,s2,o); }
    if (lane==0){ red[wid]=s1; red[8+wid]=s2; }
    __syncthreads();
    if (tid==0){ float a1=0,a2=0; for(int k=0;k<8;k++){a1+=red[k];a2+=red[8+k];} red[0]=a1; red[8]=a2; }
    __syncthreads();
    float mean = red[0]*(1.0f/D_);
    float var  = red[8]*(1.0f/D_) - mean*mean;
    float rstd = rsqrtf(var + 1e-5f);
    float ss = 0.f;
    #pragma unroll
    for (int i=0;i<6;i++) {
        int e = tid + i*256;
        float y = (vals[i]-mean)*rstd*w[e] + bb[e];
        out[(size_t)row*D_+e] = y;
        ss += y*y;
    }
    if (norm_out) {
        for (int o=16;o;o>>=1) ss+=__shfl_xor_sync(~0u,ss,o);
        __syncthreads();
        if (lane==0) red[wid]=ss;
        __syncthreads();
        if (tid==0){ float t=0; for(int k=0;k<8;k++) t+=red[k]; norm_out[row]=sqrtf(t); }
    }
}

// ---------------- CA: scores[b,h,s] = mem[b,s]·g[b,h] / sqrt(DH) ---------------
__global__ void __launch_bounds__(256) ca_scores_kernel(const float* __restrict__ mem)
{
    __shared__ float gs[NH_*D_];   // 48 KB
    const int b = blockIdx.x, tid = threadIdx.x;
    const float4* gsrc = (const float4*)(g_g + (size_t)b*NH_*D_);
    for (int i=tid;i<NH_*D_/4;i+=256) ((float4*)gs)[i]=gsrc[i];
    __syncthreads();
    const int warp=tid>>5, lane=tid&31;
    const float* mb = mem + (size_t)b*S_*D_;
    const float scale = rsqrtf((float)DH_);
    const int sbase = blockIdx.y*128 + warp*16;
    for (int grp=0;grp<4;grp++) {
        int s0 = sbase + grp*4;
        float acc[NH_][4];
        #pragma unroll
        for (int h=0;h<NH_;h++)
            #pragma unroll
            for (int r2=0;r2<4;r2++) acc[h][r2]=0.f;
        #pragma unroll
        for (int i=0;i<12;i++) {
            int e = lane*4 + i*128;
            float4 m[4];
            #pragma unroll
            for (int r2=0;r2<4;r2++) m[r2]=*(const float4*)(mb+(size_t)(s0+r2)*D_+e);
            #pragma unroll
            for (int h=0;h<NH_;h++) {
                float4 gv=*(const float4*)(gs + h*D_ + e);
                #pragma unroll
                for (int r2=0;r2<4;r2++)
                    acc[h][r2] += gv.x*m[r2].x + gv.y*m[r2].y + gv.z*m[r2].z + gv.w*m[r2].w;
            }
        }
        #pragma unroll
        for (int h=0;h<NH_;h++)
            #pragma unroll
            for (int r2=0;r2<4;r2++) {
                float v=acc[h][r2];
                for (int o=16;o;o>>=1) v+=__shfl_xor_sync(~0u,v,o);
                if (lane==0) g_scores[((size_t)b*NH_+h)*S_ + s0+r2] = v*scale;
            }
    }
}

// ---------------- softmax over s (in place) ------------------------------------
__global__ void __launch_bounds__(256) ca_softmax_kernel()
{
    const int row=blockIdx.x, tid=threadIdx.x;
    float* sp = g_scores + (size_t)row*S_;
    float v = sp[tid];
    __shared__ float red[16];
    int lane=tid&31, wid=tid>>5;
    float m=v;
    for (int o=16;o;o>>=1) m=fmaxf(m,__shfl_xor_sync(~0u,m,o));
    if (lane==0) red[wid]=m;
    __syncthreads();
    if (tid==0){ float mm=red[0]; for(int k=1;k<8;k++) mm=fmaxf(mm,red[k]); red[0]=mm; }
    __syncthreads();
    m=red[0];
    float e=__expf(v-m);
    float s=e;
    for (int o=16;o;o>>=1) s+=__shfl_xor_sync(~0u,s,o);
    __syncthreads();
    if (lane==0) red[8+wid]=s;
    __syncthreads();
    if (tid==0){ float t=0; for(int k=0;k<8;k++) t+=red[8+k]; red[8]=t; }
    __syncthreads();
    sp[tid]=e/red[8];
}

// ---------------- m~[b,h] = sum_s attn[b,h,s] * mem[b,s,:] ---------------------
__global__ void __launch_bounds__(256) mtilde_kernel(const float* __restrict__ mem)
{
    __shared__ float at[NH_*S_];   // 8 KB
    const int b=blockIdx.x, tid=threadIdx.x;
    for (int i=tid;i<NH_*S_;i+=256) at[i]=g_scores[(size_t)b*NH_*S_+i];
    __syncthreads();
    const int e = blockIdx.y*512 + tid*2;
    const float* mb = mem + (size_t)b*S_*D_;
    float2 acc[NH_];
    #pragma unroll
    for (int h=0;h<NH_;h++){ acc[h].x=0.f; acc[h].y=0.f; }
    for (int s=0;s<S_;s++) {
        float2 mv=*(const float2*)(mb+(size_t)s*D_+e);
        #pragma unroll
        for (int h=0;h<NH_;h++){
            float a=at[h*S_+s];
            acc[h].x=fmaf(a,mv.x,acc[h].x);
            acc[h].y=fmaf(a,mv.y,acc[h].y);
        }
    }
    #pragma unroll
    for (int h=0;h<NH_;h++)
        *(float2*)(g_mt + (size_t)b*NH_*D_ + h*D_ + e) = acc[h];
}

// ---------------- ||memory[j,s]|| ----------------------------------------------
__global__ void __launch_bounds__(256) nm_kernel(const float* __restrict__ mem)
{
    int row = blockIdx.x*8 + (threadIdx.x>>5);
    int lane = threadIdx.x&31;
    const float* p = mem + (size_t)row*D_;
    float s=0.f;
    for (int e=lane*4;e<D_;e+=128){ float4 v=*(const float4*)(p+e); s+=v.x*v.x+v.y*v.y+v.z*v.z+v.w*v.w; }
    for (int o=16;o;o>>=1) s+=__shfl_xor_sync(~0u,s,o);
    if (lane==0) g_nm[row]=sqrtf(s);
}

// ---------------- build A = [qt/sqrt(D) ; x_sq] --------------------------------
__global__ void prepA_kernel()
{
    int idx = blockIdx.x*256 + threadIdx.x;  // over B_*D_
    const float sc = rsqrtf((float)D_);
    g_A[idx] = g_qt[idx]*sc;
    g_A[B_*D_+idx] = g_xsq[idx];
}

// ---------------- final reduce: softmax_s(S) weighted cosine sum ---------------
__global__ void __launch_bounds__(256) pool_reduce_kernel(
    const float* __restrict__ ls, float* __restrict__ out)
{
    const int j=blockIdx.x, i=blockIdx.y, s=threadIdx.x;
    float Sv = g_S[(size_t)i*BS_ + j*S_ + s];
    float Cv = g_S[(size_t)(B_+i)*BS_ + j*S_ + s];
    float nmv = g_nm[j*S_+s];
    __shared__ float red[16];
    int lane=s&31, wid=s>>5;
    float m=Sv;
    for (int o=16;o;o>>=1) m=fmaxf(m,__shfl_xor_sync(~0u,m,o));
    if (lane==0) red[wid]=m;
    __syncthreads();
    if (s==0){ float mm=red[0]; for(int k=1;k<8;k++) mm=fmaxf(mm,red[k]); red[0]=mm; }
    __syncthreads();
    m=red[0];
    float e = expf(Sv-m);
    float t1=e, t2=e*Cv/nmv;
    for (int o=16;o;o>>=1){ t1+=__shfl_xor_sync(~0u,t1,o); t2+=__shfl_xor_sync(~0u,t2,o); }
    __syncthreads();
    if (lane==0){ red[wid]=t1; red[8+wid]=t2; }
    __syncthreads();
    if (s==0) {
        float Z=0.f, Wv=0.f;
        for (int k=0;k<8;k++){ Z+=red[k]; Wv+=red[8+k]; }
        float val = expf(ls[0]) * Wv / (Z * g_nx[i]);
        out[(size_t)i*B_ + j] = val;
        out[(size_t)B_*B_ + (size_t)j*B_ + i] = val;
    }
}

__global__ void copy_xsq_kernel(float* __restrict__ out)
{
    int idx = blockIdx.x*256 + threadIdx.x;
    out[(size_t)2*B_*B_ + idx] = g_xsq[idx];
}

// ---------------- host ----------------------------------------------------------
template<typename T> static float* sym(T& s){ void* p=nullptr; cudaGetSymbolAddress(&p, s); return (float*)p; }

extern "C" void kernel_launch(void* const* d_in, const int* in_sizes, int n_in,
                              void* d_out, int out_size)
{
    const float* x        =(const float*)d_in[0];
    const float* mem      =(const float*)d_in[1];
    const float* emb_w    =(const float*)d_in[2];
    const float* emb_b    =(const float*)d_in[3];
    const float* sa_in_w  =(const float*)d_in[4];
    const float* sa_in_b  =(const float*)d_in[5];
    const float* sa_out_w =(const float*)d_in[6];
    const float* sa_out_b =(const float*)d_in[7];
    const float* ca_in_w  =(const float*)d_in[8];
    const float* ca_in_b  =(const float*)d_in[9];
    const float* ca_out_w =(const float*)d_in[10];
    const float* ca_out_b =(const float*)d_in[11];
    const float* lin1_w   =(const float*)d_in[12];
    const float* lin1_b   =(const float*)d_in[13];
    const float* lin2_w   =(const float*)d_in[14];
    const float* lin2_b   =(const float*)d_in[15];
    const float* ln1_w    =(const float*)d_in[16];
    const float* ln1_b    =(const float*)d_in[17];
    const float* ln2_w    =(const float*)d_in[18];
    const float* ln2_b    =(const float*)d_in[19];
    const float* ln3_w    =(const float*)d_in[20];
    const float* ln3_b    =(const float*)d_in[21];
    const float* fin_w    =(const float*)d_in[22];
    const float* fin_b    =(const float*)d_in[23];
    const float* attn_in_w=(const float*)d_in[24];
    const float* attn_in_b=(const float*)d_in[25];
    const float* logit_sc =(const float*)d_in[26];
    float* out = (float*)d_out;

    float* t0 = sym(g_t0);  float* v   = sym(g_v);   float* sa  = sym(g_sa);
    float* t1 = sym(g_t1);  float* qp  = sym(g_qp);  float* gg  = sym(g_g);
    float* mt = sym(g_mt);  float* o   = sym(g_o);   float* ca  = sym(g_ca);
    float* t2 = sym(g_t2);  float* h1  = sym(g_h1);  float* ff  = sym(g_ff);
    float* t3 = sym(g_t3);  float* xsq = sym(g_xsq); float* qp2 = sym(g_qp2);
    float* qt = sym(g_qt);  float* Am  = sym(g_A);   float* Sm  = sym(g_S);
    float* nx = sym(g_nx);

    // 1. t0 = x @ emb_w.T + emb_b
    gemm_nt<64,64,16,4,4,false><<<dim3(D_/64, B_/64), 256>>>(x, DIN_, emb_w, DIN_, emb_b, t0, D_, DIN_);
    // 2. SA (L=1): v = t0 @ wv.T + bv ; sa = v @ out_w.T + out_b
    gemm_nt<64,64,16,4,4,false><<<dim3(D_/64, B_/64), 256>>>(t0, D_, sa_in_w + (size_t)2*D_*D_, D_, sa_in_b + 2*D_, v, D_, D_);
    gemm_nt<64,64,16,4,4,false><<<dim3(D_/64, B_/64), 256>>>(v, D_, sa_out_w, D_, sa_out_b, sa, D_, D_);
    // 3. t1 = LN(t0 + sa)
    ln_kernel<<<B_, 256>>>(t0, sa, ln1_w, ln1_b, t1, nullptr);
    // 4. CA q-proj, then g[b,h] = qp_h @ wk_h
    gemm_nt<64,64,16,4,4,false><<<dim3(D_/64, B_/64), 256>>>(t1, D_, ca_in_w, D_, ca_in_b, qp, D_, D_);
    for (int h=0;h<NH_;h++)
        gemm_nn<64,64,16,4,4><<<dim3(D_/64, B_/64), 256>>>(qp + h*DH_, D_,
            ca_in_w + (size_t)(D_ + h*DH_)*D_, D_, nullptr, gg + (size_t)h*D_, NH_*D_, DH_);
    // 5. CA scores / softmax / weighted memory
    ca_scores_kernel<<<dim3(B_,2), 256>>>(mem);
    ca_softmax_kernel<<<B_*NH_, 256>>>();
    mtilde_kernel<<<dim3(B_,3), 256>>>(mem);
    // 6. o_h = m~_h @ wv_h.T + bv_h ; ca = o @ out_w.T + out_b
    for (int h=0;h<NH_;h++)
        gemm_nt<64,64,16,4,4,false><<<dim3(DH_/64, B_/64), 256>>>(mt + (size_t)h*D_, NH_*D_,
            ca_in_w + (size_t)(2*D_ + h*DH_)*D_, D_, ca_in_b + 2*D_ + h*DH_, o + h*DH_, D_, D_);
    gemm_nt<64,64,16,4,4,false><<<dim3(D_/64, B_/64), 256>>>(o, D_, ca_out_w, D_, ca_out_b, ca, D_, D_);
    // 7. t2 = LN(t1 + ca)
    ln_kernel<<<B_, 256>>>(t1, ca, ln2_w, ln2_b, t2, nullptr);
    // 8. FF
    gemm_nt<64,64,16,4,4,true ><<<dim3(FF_/64, B_/64), 256>>>(t2, D_, lin1_w, D_, lin1_b, h1, FF_, D_);
    gemm_nt<64,64,16,4,4,false><<<dim3(D_/64, B_/64), 256>>>(h1, FF_, lin2_w, FF_, lin2_b, ff, D_, FF_);
    // 9. t3 = LN(t2 + ff) ; x_sq = LN(t3) with row norm
    ln_kernel<<<B_, 256>>>(t2, ff, ln3_w, ln3_b, t3, nullptr);
    ln_kernel<<<B_, 256>>>(t3, nullptr, fin_w, fin_b, xsq, nx);
    // 10. pooling: qp2 = x_sq@wq2.T+bq2 ; qt = qp2@wk2 (bias cancels in softmax)
    gemm_nt<64,64,16,4,4,false><<<dim3(D_/64, B_/64), 256>>>(xsq, D_, attn_in_w, D_, attn_in_b, qp2, D_, D_);
    gemm_nn<64,64,16,4,4><<<dim3(D_/64, B_/64), 256>>>(qp2, D_, attn_in_w + (size_t)D_*D_, D_, nullptr, qt, D_, D_);
    prepA_kernel<<<(B_*D_)/256, 256>>>();
    nm_kernel<<<BS_/8, 256>>>(mem);
    // 11. big GEMM: [qt/sqrt(D); x_sq] (256x1536) @ memory^T (1536x32768)
    gemm_nt<128,128,16,8,8,false><<<dim3(BS_/128, 2*B_/128), 256>>>(Am, D_, mem, D_, nullptr, Sm, BS_, D_);
    // 12. final softmax-weighted cosine reduce + transpose write
    pool_reduce_kernel<<<dim3(B_, B_), 256>>>(logit_sc, out);
    // 13. third output
    copy_xsq_kernel<<<(B_*D_)/256, 256>>>(out);

    (void)in_sizes; (void)n_in; (void)out_size;
}